// round 16
// baseline (speedup 1.0000x reference)
#include <cuda_runtime.h>
#include <math.h>

#define TT 512
#define BB 256
#define DD 128
#define HH 256
#define DHW 384   // D + H
#define G4 1024   // 4*H

// ---------------- scratch (static device allocations; no cudaMalloc) ---------
__device__ float g_zx[(size_t)TT * BB * G4];   // 536 MB: input projection, gate-major
__device__ float g_hs[(size_t)TT * BB * HH];   // 134 MB: h_t for every step
__device__ unsigned g_flag[8][TT][16];         // per-(b-group, step, producer) flags

// ---------------- packed fp32x2 FMA -----------------------------------------
__device__ __forceinline__ void ffma2(unsigned long long& d,
                                      unsigned long long a,
                                      unsigned long long b) {
    asm("fma.rn.f32x2 %0, %1, %2, %0;" : "+l"(d) : "l"(a), "l"(b));
}
__device__ __forceinline__ float unpack_sum(unsigned long long v) {
    unsigned lo, hi;
    asm("mov.b64 {%0,%1}, %2;" : "=r"(lo), "=r"(hi) : "l"(v));
    return __uint_as_float(lo) + __uint_as_float(hi);
}

__device__ __forceinline__ float sigf(float x) {
    return __fdividef(1.0f, 1.0f + __expf(-x));
}
__device__ __forceinline__ float tanh_fast(float x) {
    return fmaf(2.0f, __fdividef(1.0f, 1.0f + __expf(-2.0f * x)), -1.0f);
}

// =============================================================================
// Kernel 0: zero the readiness flags (graph replays reuse them)
// =============================================================================
__global__ void zero_kernel() {
    int i = blockIdx.x * blockDim.x + threadIdx.x;
    if (i < 8 * TT * 16) ((unsigned*)g_flag)[i] = 0u;
}

// =============================================================================
// Kernel 1: Zx = X @ W[:, :D]^T + b. M=131072, N=1024, K=128.  (R12-exact)
// Block 128(M) x 64(N), thread 8x4, packed f32x2, occ 2.
// Grid (nt fastest): 16 blocks share one X tile in L2.
// =============================================================================
#define ZX_MT 128
#define ZX_NT 64
#define ZX_PAD 132
#define ZX_SMEM (((ZX_MT + ZX_NT) * ZX_PAD) * 4)

__global__ void __launch_bounds__(256, 2) zx_kernel(
    const float* __restrict__ x,
    const float* __restrict__ Wf, const float* __restrict__ bf,
    const float* __restrict__ Wi, const float* __restrict__ bi,
    const float* __restrict__ Wg, const float* __restrict__ bg,
    const float* __restrict__ Wo, const float* __restrict__ bo)
{
    extern __shared__ float sm[];
    float* Xs = sm;                       // [128][132]
    float* Ws = sm + ZX_MT * ZX_PAD;      // [64][132]
    const int tid = threadIdx.x;
    const int nt = blockIdx.x;            // 0..15 (fast: shares X tile)
    const int mt = blockIdx.y;            // 0..1023
    const int gate = nt >> 2;
    const int jb = (nt & 3) * 64;

    const float* Wp = (gate == 0) ? Wf : (gate == 1) ? Wi : (gate == 2) ? Wg : Wo;
    const float* bp = (gate == 0) ? bf : (gate == 1) ? bi : (gate == 2) ? bg : bo;

    for (int idx = tid; idx < ZX_MT * 32; idx += 256) {
        int r = idx >> 5, k4 = idx & 31;
        float4 v = ((const float4*)x)[((size_t)(mt * ZX_MT + r)) * 32 + k4];
        *(float4*)&Xs[r * ZX_PAD + 4 * k4] = v;
    }
    for (int idx = tid; idx < ZX_NT * 32; idx += 256) {
        int r = idx >> 5, k4 = idx & 31;
        float4 v = *(const float4*)&Wp[(size_t)(jb + r) * DHW + 4 * k4];
        *(float4*)&Ws[r * ZX_PAD + 4 * k4] = v;
    }
    __syncthreads();

    const int ty = tid >> 4;   // 0..15 -> 8 rows
    const int tx = tid & 15;   // 0..15 -> 4 cols (stride 16)

    unsigned long long acc[8][4];
    #pragma unroll
    for (int r = 0; r < 8; r++)
        #pragma unroll
        for (int jj = 0; jj < 4; jj++) acc[r][jj] = 0ull;

    #pragma unroll 2
    for (int k4 = 0; k4 < 32; k4++) {
        ulonglong2 a[8], w[4];
        #pragma unroll
        for (int r = 0; r < 8; r++)
            a[r] = *(const ulonglong2*)&Xs[(ty * 8 + r) * ZX_PAD + 4 * k4];
        #pragma unroll
        for (int jj = 0; jj < 4; jj++)
            w[jj] = *(const ulonglong2*)&Ws[(tx + 16 * jj) * ZX_PAD + 4 * k4];
        #pragma unroll
        for (int r = 0; r < 8; r++)
            #pragma unroll
            for (int jj = 0; jj < 4; jj++) {
                ffma2(acc[r][jj], a[r].x, w[jj].x);
                ffma2(acc[r][jj], a[r].y, w[jj].y);
            }
    }

    #pragma unroll
    for (int r = 0; r < 8; r++) {
        size_t m = (size_t)mt * ZX_MT + ty * 8 + r;
        float* dst = &g_zx[m * G4 + (size_t)gate * HH + jb];
        #pragma unroll
        for (int jj = 0; jj < 4; jj++)
            dst[tx + 16 * jj] = unpack_sum(acc[r][jj]) + bp[jb + tx + 16 * jj];
    }
}

// =============================================================================
// Kernel 2: persistent LSTM recurrence. 128 CTAs = 8 b-groups x 16 j-tiles.
// R12 base with DEPENDENCY-SPARSIFIED sync: consumer warp ksl reads h columns
// [32ksl, 32ksl+32) = output of producers jx = 2ksl, 2ksl+1 ONLY. Each warp
// acquire-polls just its 2 per-producer flags (one aligned u64), then stages
// its private slice and runs its GEMM; barrier(A) reconverges before the
// reduce. Producer release = single st.release per CTA (single-writer flag,
// distinct addresses -> no serialization).
// =============================================================================
#define SH_STRIDE 260            // staged h rows
#define SP_STRIDE 521            // partials rows (odd -> bank spread)
#define SW_F   (64 * SH_STRIDE)  // 16640 floats
#define SHIN_F (32 * SH_STRIDE)  //  8320
#define SP_F   (32 * SP_STRIDE)  // 16672
#define LSTM_SMEM ((SW_F + SHIN_F + SP_F) * 4)   // 166528 B

__global__ void __launch_bounds__(256, 1) lstm_kernel(
    const float* __restrict__ Wf, const float* __restrict__ Wi,
    const float* __restrict__ Wg, const float* __restrict__ Wo,
    float* __restrict__ out)
{
    extern __shared__ float sm[];
    float* sW   = sm;                    // [64][260]  rows: g*16 + jl
    float* sHin = sm + SW_F;             // [32][260]
    float* sP   = sHin + SHIN_F;         // [32][521]: b*521 + ksl*64 + col

    const int tid = threadIdx.x;
    const int bx = blockIdx.x;           // 0..7  (b-group of 32 rows)
    const int jx = blockIdx.y;           // 0..15 (j-tile of 16)
    const int btile = bx * 32;
    const int jtile = jx * 16;

    // Load recurrent weight slab once: row r = g*16+jl <- Wg[jtile+jl, D:D+H]
    const float* Wptr[4] = {Wf, Wi, Wg, Wo};
    for (int idx = tid; idx < 64 * 64; idx += 256) {
        int r = idx >> 6, k4 = idx & 63;
        const float* Wp = Wptr[r >> 4];
        int j = jtile + (r & 15);
        float4 v = *(const float4*)&Wp[(size_t)j * DHW + DD + 4 * k4];
        *(float4*)&sW[r * SH_STRIDE + 4 * k4] = v;
    }
    __syncthreads();

    // ---- GEMM decomposition: tid = ksl*32 + bq*8 + jq (ksl == warp id) ----
    const int jq  = tid & 7;          // 0..7  output-j offset
    const int bq  = (tid >> 3) & 3;   // 0..3  8-row b block
    const int ksl = tid >> 5;         // 0..7  k-slice of 32 (== warp)
    const int lane = tid & 31;
    const int sr0 = lane >> 3;        // 0..3  staging row phase
    const int sc4 = lane & 7;         // 0..7  staging col (float4)

    const float* wbase[8];            // rows g*16 + jq + 8u, at this k-slice
    #pragma unroll
    for (int g = 0; g < 4; g++)
        #pragma unroll
        for (int u = 0; u < 2; u++)
            wbase[g * 2 + u] = &sW[(g * 16 + jq + 8 * u) * SH_STRIDE + ksl * 32];
    const float* hbase = &sHin[(bq * 8) * SH_STRIDE + ksl * 32];

    // ---- reduction / gate decomposition: (bl, q) ----
    const int q  = tid & 7;           // 0..7
    const int bl = tid >> 3;          // 0..31
    const int b  = btile + bl;
    const int j0 = jtile + q;         // owns j0 and j0+8

    float c0 = 0.0f, c1 = 0.0f;
    float* out_hx = out + (size_t)TT * BB * 2;
    float* out_cx = out_hx + (size_t)BB * HH;

    // z for t=0
    float z[8];
    {
        const float* zx0 = &g_zx[(size_t)b * G4 + j0];
        #pragma unroll
        for (int g = 0; g < 4; g++) {
            z[g * 2]     = zx0[g * HH];
            z[g * 2 + 1] = zx0[g * HH + 8];
        }
    }

    for (int t = 0; t < TT; t++) {
        // prefetch z_{t+1} (in flight during poll + stage + GEMM)
        float zn[8];
        if (t + 1 < TT) {
            const float* zx1 = &g_zx[((size_t)(t + 1) * BB + b) * G4 + j0];
            #pragma unroll
            for (int g = 0; g < 4; g++) {
                zn[g * 2]     = zx1[g * HH];
                zn[g * 2 + 1] = zx1[g * HH + 8];
            }
        }

        if (t > 0) {
            // per-warp poll: only this warp's 2 producers (jx = 2ksl, 2ksl+1).
            // Flags are adjacent u32s at an 8B-aligned address -> one u64
            // acquire load per iteration.
            {
                const unsigned long long* fp = (const unsigned long long*)
                    &g_flag[bx][t - 1][2 * ksl];
                unsigned long long v;
                do {
                    asm volatile("ld.acquire.gpu.u64 %0, [%1];"
                                 : "=l"(v) : "l"(fp) : "memory");
                } while (v != 0x0000000100000001ull);
            }
            // stage THIS warp's k-slice of h_{t-1}: 32 rows x 32 k (private)
            const float* hprev =
                &g_hs[((size_t)(t - 1) * BB + btile) * HH + ksl * 32];
            #pragma unroll
            for (int i = 0; i < 8; i++) {
                int r = i * 4 + sr0;
                float4 v = *(const float4*)&hprev[(size_t)r * HH + 4 * sc4];
                *(float4*)&sHin[r * SH_STRIDE + ksl * 32 + 4 * sc4] = v;
            }
            __syncwarp();

            // ---- k-sliced GEMM: 8b x 8(g,u) x 32k per thread ----
            unsigned long long acc[8][8];
            #pragma unroll
            for (int rb = 0; rb < 8; rb++)
                #pragma unroll
                for (int i = 0; i < 8; i++) acc[rb][i] = 0ull;

            #pragma unroll
            for (int k4i = 0; k4i < 8; k4i++) {
                const int k4 = (k4i + 2 * bq) & 7;   // bq-rotated: conflict-free
                ulonglong2 hv[8], wv[8];
                #pragma unroll
                for (int rb = 0; rb < 8; rb++)
                    hv[rb] = *(const ulonglong2*)(hbase + rb * SH_STRIDE + 4 * k4);
                #pragma unroll
                for (int i = 0; i < 8; i++)
                    wv[i] = *(const ulonglong2*)(wbase[i] + 4 * k4);
                #pragma unroll
                for (int rb = 0; rb < 8; rb++)
                    #pragma unroll
                    for (int i = 0; i < 8; i++) {
                        ffma2(acc[rb][i], hv[rb].x, wv[i].x);
                        ffma2(acc[rb][i], hv[rb].y, wv[i].y);
                    }
            }

            // write partials: sP[b*521 + ksl*64 + col], col = g*16 + jq + 8u
            #pragma unroll
            for (int rb = 0; rb < 8; rb++) {
                float* pr = &sP[(bq * 8 + rb) * SP_STRIDE + ksl * 64];
                #pragma unroll
                for (int g = 0; g < 4; g++)
                    #pragma unroll
                    for (int u = 0; u < 2; u++)
                        pr[g * 16 + jq + 8 * u] =
                            unpack_sum(acc[rb][g * 2 + u]);
            }
        }

        __syncthreads();   // (A) partials visible block-wide

        float s[8];
        if (t > 0) {
            // reduce the 8 k-slices per output
            #pragma unroll
            for (int g = 0; g < 4; g++)
                #pragma unroll
                for (int u = 0; u < 2; u++) {
                    const float* pr = &sP[bl * SP_STRIDE + g * 16 + q + 8 * u];
                    float a0 = pr[0]       + pr[64];
                    float a1 = pr[2 * 64]  + pr[3 * 64];
                    float a2 = pr[4 * 64]  + pr[5 * 64];
                    float a3 = pr[6 * 64]  + pr[7 * 64];
                    s[g * 2 + u] = (a0 + a1) + (a2 + a3);
                }
        } else {
            #pragma unroll
            for (int i = 0; i < 8; i++) s[i] = 0.0f;
        }

        float f0 = sigf(z[0] + s[0]);
        float f1 = sigf(z[1] + s[1]);
        float i0 = sigf(z[2] + s[2]);
        float i1 = sigf(z[3] + s[3]);
        float g0 = tanh_fast(z[4] + s[4]);
        float g1 = tanh_fast(z[5] + s[5]);
        float o0 = sigf(z[6] + s[6]);
        float o1 = sigf(z[7] + s[7]);

        c0 = fmaf(f0, c0, i0 * g0);
        c1 = fmaf(f1, c1, i1 * g1);
        float h0 = o0 * tanh_fast(c0);
        float h1 = o1 * tanh_fast(c1);

        // direct publish (4 x 32B sectors per warp per store)
        float* hdst = &g_hs[((size_t)t * BB + b) * HH];
        hdst[j0]     = h0;
        hdst[j0 + 8] = h1;

        if (t == TT - 1) {
            out_hx[(size_t)b * HH + j0]     = h0;
            out_hx[(size_t)b * HH + j0 + 8] = h1;
            out_cx[(size_t)b * HH + j0]     = c0;
            out_cx[(size_t)b * HH + j0 + 8] = c1;
        }

        __syncthreads();   // (B) all publish STGs issued before the release
        if (t < TT - 1 && tid == 0) {
            const unsigned* fp = &g_flag[bx][t][jx];
            asm volatile("st.release.gpu.u32 [%0], %1;"
                         :: "l"(fp), "r"(1u) : "memory");
        }

        #pragma unroll
        for (int i = 0; i < 8; i++) z[i] = zn[i];
    }
}

// =============================================================================
// Kernel 3: probs = sigmoid(hs . Wc + bc); out[...,1] = 1 - p. Memory-bound.
// =============================================================================
__global__ void __launch_bounds__(256) logits_kernel(
    const float* __restrict__ Wc, const float* __restrict__ bc,
    float* __restrict__ out)
{
    const int lane = threadIdx.x & 31;
    const size_t row = ((size_t)blockIdx.x * blockDim.x + threadIdx.x) >> 5;
    if (row >= (size_t)TT * BB) return;

    const float4* hv4 = (const float4*)(g_hs + row * HH);
    const float4* wv4 = (const float4*)Wc;

    float s = 0.0f;
    #pragma unroll
    for (int i = 0; i < 2; i++) {
        float4 hv = hv4[lane + 32 * i];
        float4 wv = wv4[lane + 32 * i];
        s += hv.x * wv.x + hv.y * wv.y + hv.z * wv.z + hv.w * wv.w;
    }
    #pragma unroll
    for (int off = 16; off > 0; off >>= 1)
        s += __shfl_xor_sync(0xffffffffu, s, off);

    if (lane == 0) {
        float p = 1.0f / (1.0f + expf(-(s + bc[0])));
        out[2 * row]     = p;
        out[2 * row + 1] = 1.0f - p;
    }
}

// =============================================================================
extern "C" void kernel_launch(void* const* d_in, const int* in_sizes, int n_in,
                              void* d_out, int out_size)
{
    const float* x  = (const float*)d_in[0];
    const float* Wf = (const float*)d_in[1];
    const float* bf = (const float*)d_in[2];
    const float* Wi = (const float*)d_in[3];
    const float* bi = (const float*)d_in[4];
    const float* Wg = (const float*)d_in[5];
    const float* bg = (const float*)d_in[6];
    const float* Wo = (const float*)d_in[7];
    const float* bo = (const float*)d_in[8];
    const float* Wc = (const float*)d_in[9];
    const float* bc = (const float*)d_in[10];
    float* out = (float*)d_out;

    cudaFuncSetAttribute(zx_kernel,   cudaFuncAttributeMaxDynamicSharedMemorySize, ZX_SMEM);
    cudaFuncSetAttribute(lstm_kernel, cudaFuncAttributeMaxDynamicSharedMemorySize, LSTM_SMEM);

    zero_kernel<<<(8 * TT * 16 + 255) / 256, 256>>>();

    zx_kernel<<<dim3(G4 / ZX_NT, (TT * BB) / ZX_MT), 256, ZX_SMEM>>>(
        x, Wf, bf, Wi, bi, Wg, bg, Wo, bo);

    lstm_kernel<<<dim3(8, 16), 256, LSTM_SMEM>>>(Wf, Wi, Wg, Wo, out);

    logits_kernel<<<(TT * BB) / 8, 256>>>(Wc, bc, out);
}

// round 17
// speedup vs baseline: 1.0368x; 1.0368x over previous
#include <cuda_runtime.h>
#include <math.h>

#define TT 512
#define BB 256
#define DD 128
#define HH 256
#define DHW 384   // D + H
#define G4 1024   // 4*H

// ---------------- scratch (static device allocations; no cudaMalloc) ---------
__device__ float g_zx[(size_t)TT * BB * G4];   // 536 MB: input projection, gate-major
__device__ float g_hs[(size_t)TT * BB * HH];   // 134 MB: h_t for every step
__device__ unsigned g_cnt[8][TT];              // per-(b-group, step) arrival counters

// ---------------- packed fp32x2 FMA -----------------------------------------
__device__ __forceinline__ void ffma2(unsigned long long& d,
                                      unsigned long long a,
                                      unsigned long long b) {
    asm("fma.rn.f32x2 %0, %1, %2, %0;" : "+l"(d) : "l"(a), "l"(b));
}
__device__ __forceinline__ float unpack_sum(unsigned long long v) {
    unsigned lo, hi;
    asm("mov.b64 {%0,%1}, %2;" : "=r"(lo), "=r"(hi) : "l"(v));
    return __uint_as_float(lo) + __uint_as_float(hi);
}

__device__ __forceinline__ float sigf(float x) {
    return __fdividef(1.0f, 1.0f + __expf(-x));
}
__device__ __forceinline__ float tanh_fast(float x) {
    return fmaf(2.0f, __fdividef(1.0f, 1.0f + __expf(-2.0f * x)), -1.0f);
}

// =============================================================================
// Kernel 1: Zx = X @ W[:, :D]^T + b. M=131072, N=1024, K=128.  (R12-exact)
// Block 128(M) x 64(N), thread 8x4, packed f32x2, occ 2.
// Grid (nt fastest): 16 blocks share one X tile in L2.
// ALSO: the 16 blocks with mt==0 zero the g_cnt counters (consumed only by
// lstm_kernel, which launches after zx completes -> stream-ordered, safe).
// =============================================================================
#define ZX_MT 128
#define ZX_NT 64
#define ZX_PAD 132
#define ZX_SMEM (((ZX_MT + ZX_NT) * ZX_PAD) * 4)

__global__ void __launch_bounds__(256, 2) zx_kernel(
    const float* __restrict__ x,
    const float* __restrict__ Wf, const float* __restrict__ bf,
    const float* __restrict__ Wi, const float* __restrict__ bi,
    const float* __restrict__ Wg, const float* __restrict__ bg,
    const float* __restrict__ Wo, const float* __restrict__ bo)
{
    extern __shared__ float sm[];
    float* Xs = sm;                       // [128][132]
    float* Ws = sm + ZX_MT * ZX_PAD;      // [64][132]
    const int tid = threadIdx.x;
    const int nt = blockIdx.x;            // 0..15 (fast: shares X tile)
    const int mt = blockIdx.y;            // 0..1023
    const int gate = nt >> 2;
    const int jb = (nt & 3) * 64;

    // fold counter zeroing into this kernel (replaces zero_kernel launch)
    if (mt == 0 && tid < 256) {
        int base = nt * 256 + tid;        // 16 blocks x 256 = 4096 entries
        ((unsigned*)g_cnt)[base] = 0u;
    }

    const float* Wp = (gate == 0) ? Wf : (gate == 1) ? Wi : (gate == 2) ? Wg : Wo;
    const float* bp = (gate == 0) ? bf : (gate == 1) ? bi : (gate == 2) ? bg : bo;

    for (int idx = tid; idx < ZX_MT * 32; idx += 256) {
        int r = idx >> 5, k4 = idx & 31;
        float4 v = ((const float4*)x)[((size_t)(mt * ZX_MT + r)) * 32 + k4];
        *(float4*)&Xs[r * ZX_PAD + 4 * k4] = v;
    }
    for (int idx = tid; idx < ZX_NT * 32; idx += 256) {
        int r = idx >> 5, k4 = idx & 31;
        float4 v = *(const float4*)&Wp[(size_t)(jb + r) * DHW + 4 * k4];
        *(float4*)&Ws[r * ZX_PAD + 4 * k4] = v;
    }
    __syncthreads();

    const int ty = tid >> 4;   // 0..15 -> 8 rows
    const int tx = tid & 15;   // 0..15 -> 4 cols (stride 16)

    unsigned long long acc[8][4];
    #pragma unroll
    for (int r = 0; r < 8; r++)
        #pragma unroll
        for (int jj = 0; jj < 4; jj++) acc[r][jj] = 0ull;

    #pragma unroll 2
    for (int k4 = 0; k4 < 32; k4++) {
        ulonglong2 a[8], w[4];
        #pragma unroll
        for (int r = 0; r < 8; r++)
            a[r] = *(const ulonglong2*)&Xs[(ty * 8 + r) * ZX_PAD + 4 * k4];
        #pragma unroll
        for (int jj = 0; jj < 4; jj++)
            w[jj] = *(const ulonglong2*)&Ws[(tx + 16 * jj) * ZX_PAD + 4 * k4];
        #pragma unroll
        for (int r = 0; r < 8; r++)
            #pragma unroll
            for (int jj = 0; jj < 4; jj++) {
                ffma2(acc[r][jj], a[r].x, w[jj].x);
                ffma2(acc[r][jj], a[r].y, w[jj].y);
            }
    }

    #pragma unroll
    for (int r = 0; r < 8; r++) {
        size_t m = (size_t)mt * ZX_MT + ty * 8 + r;
        float* dst = &g_zx[m * G4 + (size_t)gate * HH + jb];
        #pragma unroll
        for (int jj = 0; jj < 4; jj++)
            dst[tx + 16 * jj] = unpack_sum(acc[r][jj]) + bp[jb + tx + 16 * jj];
    }
}

// =============================================================================
// Kernel 2: persistent LSTM recurrence (R12-exact; best measured).
// 128 CTAs = 8 b-groups x 16 j-tiles. All-lane acquire-poll (one L2 line per
// group), per-warp private h staging (warp ksl stages only the 32 k-columns it
// consumes), thread tile 8b x 8(g,u) x 32k (8-way k-split), bq-rotated
// conflict-free GEMM loads, stride-521 scalar partials, direct scalar publish,
// barrier(B) + one red.release per CTA.
// =============================================================================
#define SH_STRIDE 260            // staged h rows
#define SP_STRIDE 521            // partials rows (odd -> bank spread)
#define SW_F   (64 * SH_STRIDE)  // 16640 floats
#define SHIN_F (32 * SH_STRIDE)  //  8320
#define SP_F   (32 * SP_STRIDE)  // 16672
#define LSTM_SMEM ((SW_F + SHIN_F + SP_F) * 4)   // 166528 B

__global__ void __launch_bounds__(256, 1) lstm_kernel(
    const float* __restrict__ Wf, const float* __restrict__ Wi,
    const float* __restrict__ Wg, const float* __restrict__ Wo,
    float* __restrict__ out)
{
    extern __shared__ float sm[];
    float* sW   = sm;                    // [64][260]  rows: g*16 + jl
    float* sHin = sm + SW_F;             // [32][260]
    float* sP   = sHin + SHIN_F;         // [32][521]: b*521 + ksl*64 + col

    const int tid = threadIdx.x;
    const int bx = blockIdx.x;           // 0..7  (b-group of 32 rows)
    const int jx = blockIdx.y;           // 0..15 (j-tile of 16)
    const int btile = bx * 32;
    const int jtile = jx * 16;

    // Load recurrent weight slab once: row r = g*16+jl <- Wg[jtile+jl, D:D+H]
    const float* Wptr[4] = {Wf, Wi, Wg, Wo};
    for (int idx = tid; idx < 64 * 64; idx += 256) {
        int r = idx >> 6, k4 = idx & 63;
        const float* Wp = Wptr[r >> 4];
        int j = jtile + (r & 15);
        float4 v = *(const float4*)&Wp[(size_t)j * DHW + DD + 4 * k4];
        *(float4*)&sW[r * SH_STRIDE + 4 * k4] = v;
    }
    __syncthreads();

    // ---- GEMM decomposition: tid = ksl*32 + bq*8 + jq (ksl == warp id) ----
    const int jq  = tid & 7;          // 0..7  output-j offset
    const int bq  = (tid >> 3) & 3;   // 0..3  8-row b block
    const int ksl = tid >> 5;         // 0..7  k-slice of 32 (== warp)
    const int lane = tid & 31;
    const int sr0 = lane >> 3;        // 0..3  staging row phase
    const int sc4 = lane & 7;         // 0..7  staging col (float4)

    const float* wbase[8];            // rows g*16 + jq + 8u, at this k-slice
    #pragma unroll
    for (int g = 0; g < 4; g++)
        #pragma unroll
        for (int u = 0; u < 2; u++)
            wbase[g * 2 + u] = &sW[(g * 16 + jq + 8 * u) * SH_STRIDE + ksl * 32];
    const float* hbase = &sHin[(bq * 8) * SH_STRIDE + ksl * 32];

    // ---- reduction / gate decomposition: (bl, q) ----
    const int q  = tid & 7;           // 0..7
    const int bl = tid >> 3;          // 0..31
    const int b  = btile + bl;
    const int j0 = jtile + q;         // owns j0 and j0+8

    float c0 = 0.0f, c1 = 0.0f;
    float* out_hx = out + (size_t)TT * BB * 2;
    float* out_cx = out_hx + (size_t)BB * HH;

    // z for t=0
    float z[8];
    {
        const float* zx0 = &g_zx[(size_t)b * G4 + j0];
        #pragma unroll
        for (int g = 0; g < 4; g++) {
            z[g * 2]     = zx0[g * HH];
            z[g * 2 + 1] = zx0[g * HH + 8];
        }
    }

    for (int t = 0; t < TT; t++) {
        // prefetch z_{t+1} (in flight during poll + stage + GEMM)
        float zn[8];
        if (t + 1 < TT) {
            const float* zx1 = &g_zx[((size_t)(t + 1) * BB + b) * G4 + j0];
            #pragma unroll
            for (int g = 0; g < 4; g++) {
                zn[g * 2]     = zx1[g * HH];
                zn[g * 2 + 1] = zx1[g * HH + 8];
            }
        }

        if (t > 0) {
            // all-lane acquire-poll: one coalesced line per warp, no relay
            {
                const unsigned* cp = &g_cnt[bx][t - 1];
                unsigned v;
                do {
                    asm volatile("ld.acquire.gpu.u32 %0, [%1];"
                                 : "=r"(v) : "l"(cp) : "memory");
                } while (v < 16u);
            }
            // stage THIS warp's k-slice of h_{t-1}: 32 rows x 32 k (private)
            const float* hprev =
                &g_hs[((size_t)(t - 1) * BB + btile) * HH + ksl * 32];
            #pragma unroll
            for (int i = 0; i < 8; i++) {
                int r = i * 4 + sr0;
                float4 v = *(const float4*)&hprev[(size_t)r * HH + 4 * sc4];
                *(float4*)&sHin[r * SH_STRIDE + ksl * 32 + 4 * sc4] = v;
            }
            __syncwarp();

            // ---- k-sliced GEMM: 8b x 8(g,u) x 32k per thread ----
            unsigned long long acc[8][8];
            #pragma unroll
            for (int rb = 0; rb < 8; rb++)
                #pragma unroll
                for (int i = 0; i < 8; i++) acc[rb][i] = 0ull;

            #pragma unroll
            for (int k4i = 0; k4i < 8; k4i++) {
                const int k4 = (k4i + 2 * bq) & 7;   // bq-rotated: conflict-free
                ulonglong2 hv[8], wv[8];
                #pragma unroll
                for (int rb = 0; rb < 8; rb++)
                    hv[rb] = *(const ulonglong2*)(hbase + rb * SH_STRIDE + 4 * k4);
                #pragma unroll
                for (int i = 0; i < 8; i++)
                    wv[i] = *(const ulonglong2*)(wbase[i] + 4 * k4);
                #pragma unroll
                for (int rb = 0; rb < 8; rb++)
                    #pragma unroll
                    for (int i = 0; i < 8; i++) {
                        ffma2(acc[rb][i], hv[rb].x, wv[i].x);
                        ffma2(acc[rb][i], hv[rb].y, wv[i].y);
                    }
            }

            // write partials: sP[b*521 + ksl*64 + col], col = g*16 + jq + 8u
            #pragma unroll
            for (int rb = 0; rb < 8; rb++) {
                float* pr = &sP[(bq * 8 + rb) * SP_STRIDE + ksl * 64];
                #pragma unroll
                for (int g = 0; g < 4; g++)
                    #pragma unroll
                    for (int u = 0; u < 2; u++)
                        pr[g * 16 + jq + 8 * u] =
                            unpack_sum(acc[rb][g * 2 + u]);
            }
        }

        __syncthreads();   // (A) partials visible block-wide

        float s[8];
        if (t > 0) {
            // reduce the 8 k-slices per output
            #pragma unroll
            for (int g = 0; g < 4; g++)
                #pragma unroll
                for (int u = 0; u < 2; u++) {
                    const float* pr = &sP[bl * SP_STRIDE + g * 16 + q + 8 * u];
                    float a0 = pr[0]       + pr[64];
                    float a1 = pr[2 * 64]  + pr[3 * 64];
                    float a2 = pr[4 * 64]  + pr[5 * 64];
                    float a3 = pr[6 * 64]  + pr[7 * 64];
                    s[g * 2 + u] = (a0 + a1) + (a2 + a3);
                }
        } else {
            #pragma unroll
            for (int i = 0; i < 8; i++) s[i] = 0.0f;
        }

        float f0 = sigf(z[0] + s[0]);
        float f1 = sigf(z[1] + s[1]);
        float i0 = sigf(z[2] + s[2]);
        float i1 = sigf(z[3] + s[3]);
        float g0 = tanh_fast(z[4] + s[4]);
        float g1 = tanh_fast(z[5] + s[5]);
        float o0 = sigf(z[6] + s[6]);
        float o1 = sigf(z[7] + s[7]);

        c0 = fmaf(f0, c0, i0 * g0);
        c1 = fmaf(f1, c1, i1 * g1);
        float h0 = o0 * tanh_fast(c0);
        float h1 = o1 * tanh_fast(c1);

        // direct publish (4 x 32B sectors per warp per store)
        float* hdst = &g_hs[((size_t)t * BB + b) * HH];
        hdst[j0]     = h0;
        hdst[j0 + 8] = h1;

        if (t == TT - 1) {
            out_hx[(size_t)b * HH + j0]     = h0;
            out_hx[(size_t)b * HH + j0 + 8] = h1;
            out_cx[(size_t)b * HH + j0]     = c0;
            out_cx[(size_t)b * HH + j0 + 8] = c1;
        }

        __syncthreads();   // (B) all publish STGs issued before the release
        if (t < TT - 1 && tid == 0) {
            const unsigned* cp = &g_cnt[bx][t];
            asm volatile("red.release.gpu.add.u32 [%0], %1;"
                         :: "l"(cp), "r"(1u) : "memory");
        }

        #pragma unroll
        for (int i = 0; i < 8; i++) z[i] = zn[i];
    }
}

// =============================================================================
// Kernel 3: probs = sigmoid(hs . Wc + bc); out[...,1] = 1 - p. Memory-bound.
// =============================================================================
__global__ void __launch_bounds__(256) logits_kernel(
    const float* __restrict__ Wc, const float* __restrict__ bc,
    float* __restrict__ out)
{
    const int lane = threadIdx.x & 31;
    const size_t row = ((size_t)blockIdx.x * blockDim.x + threadIdx.x) >> 5;
    if (row >= (size_t)TT * BB) return;

    const float4* hv4 = (const float4*)(g_hs + row * HH);
    const float4* wv4 = (const float4*)Wc;

    float s = 0.0f;
    #pragma unroll
    for (int i = 0; i < 2; i++) {
        float4 hv = hv4[lane + 32 * i];
        float4 wv = wv4[lane + 32 * i];
        s += hv.x * wv.x + hv.y * wv.y + hv.z * wv.z + hv.w * wv.w;
    }
    #pragma unroll
    for (int off = 16; off > 0; off >>= 1)
        s += __shfl_xor_sync(0xffffffffu, s, off);

    if (lane == 0) {
        float p = 1.0f / (1.0f + expf(-(s + bc[0])));
        out[2 * row]     = p;
        out[2 * row + 1] = 1.0f - p;
    }
}

// =============================================================================
extern "C" void kernel_launch(void* const* d_in, const int* in_sizes, int n_in,
                              void* d_out, int out_size)
{
    const float* x  = (const float*)d_in[0];
    const float* Wf = (const float*)d_in[1];
    const float* bf = (const float*)d_in[2];
    const float* Wi = (const float*)d_in[3];
    const float* bi = (const float*)d_in[4];
    const float* Wg = (const float*)d_in[5];
    const float* bg = (const float*)d_in[6];
    const float* Wo = (const float*)d_in[7];
    const float* bo = (const float*)d_in[8];
    const float* Wc = (const float*)d_in[9];
    const float* bc = (const float*)d_in[10];
    float* out = (float*)d_out;

    cudaFuncSetAttribute(zx_kernel,   cudaFuncAttributeMaxDynamicSharedMemorySize, ZX_SMEM);
    cudaFuncSetAttribute(lstm_kernel, cudaFuncAttributeMaxDynamicSharedMemorySize, LSTM_SMEM);

    zx_kernel<<<dim3(G4 / ZX_NT, (TT * BB) / ZX_MT), 256, ZX_SMEM>>>(
        x, Wf, bf, Wi, bi, Wg, bg, Wo, bo);

    lstm_kernel<<<dim3(8, 16), 256, LSTM_SMEM>>>(Wf, Wi, Wg, Wo, out);

    logits_kernel<<<(TT * BB) / 8, 256>>>(Wc, bc, out);
}